// round 15
// baseline (speedup 1.0000x reference)
#include <cuda_runtime.h>
#include <cuda_fp16.h>
#include <cstdint>
#include <math.h>

#define NSZ 1024

// ---------------- scratch (static device globals; no runtime alloc) --------
__device__ __align__(16) __half g_Lh[8u << 20];
__device__ __align__(16) __half g_XTh[2u << 20];
__device__ __align__(16) __half g_RTh[8u << 20];
__device__ __align__(16) __half g_Ph[8u << 20];
__device__ __align__(16) float g_G[4u << 20];
__device__ int g_ctr[64];   // per-output-tile gate counters (zero-init; reset after use)

// stage holds k=64: A0 8K | A1 8K | B0 8K | B1 8K = 32K; ring depth 3 = 96K
#define NST 3
#define STAGE 32768
#define OFF_B 16384
#define GEMM_SMEM (NST * STAGE + 128)

// ---------------- PTX helpers (all baseline sm_80/90-level) -----------------
__device__ __forceinline__ uint32_t smem_u32(const void* p) {
    uint32_t a;
    asm("{ .reg .u64 t; cvta.to.shared.u64 t, %1; cvt.u32.u64 %0, t; }"
        : "=r"(a) : "l"(p));
    return a;
}
__device__ __forceinline__ void cp16(uint32_t smem, const void* g) {
    asm volatile("cp.async.cg.shared.global [%0], [%1], 16;"
                 :: "r"(smem), "l"(g));
}
__device__ __forceinline__ void mbar_init(uint32_t a, uint32_t cnt) {
    asm volatile("mbarrier.init.shared.b64 [%0], %1;" :: "r"(a), "r"(cnt) : "memory");
}
__device__ __forceinline__ void mbar_arrive(uint32_t a) {
    asm volatile("mbarrier.arrive.shared.b64 _, [%0];" :: "r"(a) : "memory");
}
__device__ __forceinline__ void cp_mbar_arrive(uint32_t a) {
    asm volatile("cp.async.mbarrier.arrive.noinc.shared.b64 [%0];" :: "r"(a) : "memory");
}
__device__ __forceinline__ void mbar_wait(uint32_t a, uint32_t phase) {
    asm volatile("{\n\t.reg .pred P;\n\tWL%=:\n\t"
                 "mbarrier.try_wait.parity.acquire.cta.shared::cta.b64 P, [%0], %1, 0x989680;\n\t"
                 "@!P bra WL%=;\n\t}" :: "r"(a), "r"(phase) : "memory");
}
__device__ __forceinline__ void ldsm_x4(uint32_t (&r)[4], uint32_t addr) {
    asm volatile("ldmatrix.sync.aligned.m8n8.x4.shared.b16 {%0,%1,%2,%3}, [%4];"
                 : "=r"(r[0]), "=r"(r[1]), "=r"(r[2]), "=r"(r[3]) : "r"(addr));
}
__device__ __forceinline__ void mma16816(float (&d)[4], const uint32_t (&a)[4],
                                         uint32_t b0, uint32_t b1) {
    asm volatile("mma.sync.aligned.m16n8k16.row.col.f32.f16.f16.f32 "
                 "{%0,%1,%2,%3}, {%4,%5,%6,%7}, {%8,%9}, {%0,%1,%2,%3};"
                 : "+f"(d[0]), "+f"(d[1]), "+f"(d[2]), "+f"(d[3])
                 : "r"(a[0]), "r"(a[1]), "r"(a[2]), "r"(a[3]), "r"(b0), "r"(b1));
}

// swizzle: 16B chunk j within 64B row r -> j ^ ((r>>1)&3)
__device__ __forceinline__ uint32_t sw_off(int r, int j) {
    return (uint32_t)(r * 64 + ((j ^ ((r >> 1) & 3)) << 4));
}

// load one [128 rows x 32 k] fp16 tile into swizzled SMEM via cp.async
__device__ __forceinline__ void issue_mat(const __half* __restrict__ src,
                                          int row0, int k0, uint32_t dst, int tid) {
    #pragma unroll
    for (int i = 0; i < 2; i++) {
        int f = tid + i * 256;
        int r = f >> 2;
        int j = f & 3;
        cp16(dst + sw_off(r, j), src + (size_t)(row0 + r) * NSZ + k0 + j * 8);
    }
}

// issue one k=64 stage (two k=32 sub-tiles per matrix)
__device__ __forceinline__ void issue_stage(uint32_t base,
    const __half* Ah, const __half* Bh, int rowTile, int colTile, int k0, int tid)
{
    issue_mat(Ah, rowTile, k0,      base,                tid);
    issue_mat(Ah, rowTile, k0 + 32, base + 8192,         tid);
    issue_mat(Bh, colTile, k0,      base + OFF_B,        tid);
    issue_mat(Bh, colTile, k0 + 32, base + OFF_B + 8192, tid);
}

// ---------------- 64x64 transpose+convert: dst[n][k] = src[k][n] ------------
// t: 64*65 floats of SMEM. Coalesced float4 reads, 128B/warp half2 writes.
__device__ __forceinline__ void transpose64(const float* __restrict__ src,
                                            __half* __restrict__ dst,
                                            int k0, int n0, float* t, int tid)
{
    #pragma unroll
    for (int i = 0; i < 4; i++) {
        int f = tid + i * 256;
        int kk = f >> 4;               // 0..63
        int c4 = (f & 15) << 2;        // 0..60
        float4 v = *(const float4*)(src + (size_t)(k0 + kk) * NSZ + n0 + c4);
        t[kk * 65 + c4 + 0] = v.x;
        t[kk * 65 + c4 + 1] = v.y;
        t[kk * 65 + c4 + 2] = v.z;
        t[kk * 65 + c4 + 3] = v.w;
    }
    __syncthreads();
    #pragma unroll
    for (int i = 0; i < 8; i++) {
        int f = tid + i * 256;
        int nn = f >> 5;               // 0..63
        int p  = f & 31;               // k-pair 0..31
        __half2 hp = __floats2half2_rn(t[(2 * p) * 65 + nn], t[(2 * p + 1) * 65 + nn]);
        *(uint32_t*)(dst + (size_t)(n0 + nn) * NSZ + k0 + 2 * p) = *(uint32_t*)&hp;
    }
    __syncthreads();   // safe reuse of t
}

// ---------------- fp16 GEMM mainloop (k=64 stages, mbarrier ring depth 3) ---
__device__ __forceinline__ void mainloop(
    uint32_t sb, int tid, int nhalf,
    const __half* const* Ah, const __half* const* Bh,
    int rowTile, int colTile, float (&acc)[2][8][4])
{
    const uint32_t fullB  = sb + NST * STAGE;
    const uint32_t emptyB = fullB + NST * 8;

    const int lane = tid & 31;
    const int wid  = tid >> 5;
    const int wm   = wid >> 1;       // 0..3  (32 rows)
    const int wn   = wid & 1;        // 0..1  (64 cols)

    if (tid == 0) {
        #pragma unroll
        for (int b = 0; b < NST; b++) {
            mbar_init(fullB  + b * 8, 256);
            mbar_init(emptyB + b * 8, 256);
        }
    }
    __syncthreads();   // inits visible before any arrive

    uint32_t aOff[2][2], bOff[2][4];
    #pragma unroll
    for (int ks = 0; ks < 2; ks++) {
        #pragma unroll
        for (int mt = 0; mt < 2; mt++) {
            int r = wm * 32 + mt * 16 + (lane & 15);
            int j = ks * 2 + (lane >> 4);
            aOff[ks][mt] = sw_off(r, j);
        }
        #pragma unroll
        for (int bp = 0; bp < 4; bp++) {
            int r = wn * 64 + bp * 16 + ((lane >> 4) * 8) + (lane & 7);
            int j = ks * 2 + ((lane >> 3) & 1);
            bOff[ks][bp] = sw_off(r, j);
        }
    }

    const int NS = 16 * nhalf;   // k=64 stages

    #pragma unroll
    for (int s = 0; s < NST; s++) {
        issue_stage(sb + s * STAGE, Ah[0], Bh[0], rowTile, colTile, s * 64, tid);
        cp_mbar_arrive(fullB + s * 8);
    }

    uint32_t fmask = 0, emask = 0;
    int b = 0;
    #pragma unroll 1
    for (int s = 0; s < NS; s++) {
        mbar_wait(fullB + b * 8, (fmask >> b) & 1);
        fmask ^= 1u << b;

        const uint32_t base = sb + b * STAGE;
        #pragma unroll
        for (int sub = 0; sub < 2; sub++) {
            const uint32_t abase = base + sub * 8192;
            const uint32_t bbase = base + OFF_B + sub * 8192;
            #pragma unroll
            for (int ks = 0; ks < 2; ks++) {
                uint32_t Af[2][4], Bf[4][4];
                #pragma unroll
                for (int mt = 0; mt < 2; mt++) ldsm_x4(Af[mt], abase + aOff[ks][mt]);
                #pragma unroll
                for (int bp = 0; bp < 4; bp++) ldsm_x4(Bf[bp], bbase + bOff[ks][bp]);
                if (sub == 1 && ks == 1) mbar_arrive(emptyB + b * 8);

                #pragma unroll
                for (int mt = 0; mt < 2; mt++)
                    #pragma unroll
                    for (int nt = 0; nt < 8; nt++)
                        mma16816(acc[mt][nt], Af[mt],
                                 Bf[nt >> 1][(nt & 1) * 2], Bf[nt >> 1][(nt & 1) * 2 + 1]);
            }
        }

        const int sn = s + NST;
        if (sn < NS) {
            mbar_wait(emptyB + b * 8, (emask >> b) & 1);
            emask ^= 1u << b;
            const int hf = sn >> 4;
            const int k0 = (sn & 15) * 64;
            issue_stage(base, Ah[hf], Bh[hf], rowTile, colTile, k0, tid);
            cp_mbar_arrive(fullB + b * 8);
        }
        b = (b + 1 == NST) ? 0 : b + 1;
    }
}

// ---------------- Kernel: phase 1  P_g = Lh @ Xh  (+ hidden R conversion) ---
struct PR { const float* R[8]; };

__global__ void __launch_bounds__(256, 2)
gemm1(PR pr)
{
    extern __shared__ char smem[];
    const int tid = threadIdx.x;

    if (blockIdx.z == 8) {
        // R-conversion CTAs: transpose 8 R matrices into g_RTh, hidden under
        // the tensor-bound gemm CTAs. gemm2 (the consumer) launches after
        // this kernel completes.
        float* t = (float*)smem;
        const int cta = blockIdx.y * 8 + blockIdx.x;     // 0..63
        #pragma unroll 1
        for (int i = 0; i < 32; i++) {
            const int tg = cta * 32 + i;                 // 0..2047
            const int g = tg >> 8;
            const int tile = tg & 255;
            const int k0 = (tile & 15) * 64, n0 = (tile >> 4) * 64;
            transpose64(pr.R[g], g_RTh + ((size_t)g << 20), k0, n0, t, tid);
        }
        return;
    }

    const uint32_t sb = smem_u32(smem);
    const int gate = blockIdx.z;
    const int rowTile = blockIdx.y * 128, colTile = blockIdx.x * 128;

    float acc[2][8][4];
    #pragma unroll
    for (int a = 0; a < 2; a++)
        #pragma unroll
        for (int b = 0; b < 8; b++)
            #pragma unroll
            for (int e = 0; e < 4; e++) acc[a][b][e] = 0.0f;

    const __half* Ah[2] = { g_Lh  + ((size_t)gate << 20), nullptr };
    const __half* Bh[2] = { g_XTh + ((size_t)(gate & 1) << 20), nullptr };

    mainloop(sb, tid, 1, Ah, Bh, rowTile, colTile, acc);

    // epilogue: store P as fp16
    const int lane = tid & 31, wid = tid >> 5;
    const int wm = wid >> 1, wn = wid & 1;
    __half* dh = g_Ph + ((size_t)gate << 20);
    const int m0 = rowTile + wm * 32 + (lane >> 2);
    const int n0 = colTile + wn * 64 + (lane & 3) * 2;
    #pragma unroll
    for (int mt = 0; mt < 2; mt++)
        #pragma unroll
        for (int h2 = 0; h2 < 2; h2++) {
            const int m = m0 + mt * 16 + h2 * 8;
            const size_t rowb = (size_t)m * NSZ;
            #pragma unroll
            for (int nt = 0; nt < 8; nt++) {
                __half2 hp = __floats2half2_rn(acc[mt][nt][h2 * 2 + 0],
                                               acc[mt][nt][h2 * 2 + 1]);
                *(uint32_t*)(dh + rowb + n0 + nt * 8) = *(uint32_t*)&hp;
            }
        }
}

// ---------------- Kernel: phase 2  gates + fused LSTM cell -------------------
struct B8 { const float* b[8]; };

__global__ void __launch_bounds__(256, 2)
gemm2(B8 pb, const float* __restrict__ cin, float* __restrict__ out)
{
    extern __shared__ char smem[];
    const uint32_t sb = smem_u32(smem);
    const int tid = threadIdx.x;
    const int pr = blockIdx.z;                 // 0:i 1:f 2:g 3:o
    const int g0 = 2 * pr;
    const int rowTile = blockIdx.y * 128, colTile = blockIdx.x * 128;

    float acc[2][8][4];
    #pragma unroll
    for (int a = 0; a < 2; a++)
        #pragma unroll
        for (int b = 0; b < 8; b++)
            #pragma unroll
            for (int e = 0; e < 4; e++) acc[a][b][e] = 0.0f;

    const __half* Ah[2] = { g_Ph  + ((size_t)g0 << 20), g_Ph  + ((size_t)(g0 + 1) << 20) };
    const __half* Bh[2] = { g_RTh + ((size_t)g0 << 20), g_RTh + ((size_t)(g0 + 1) << 20) };

    mainloop(sb, tid, 2, Ah, Bh, rowTile, colTile, acc);

    // epilogue: + b0 + b1, activation, store fp32 gate
    const int lane = tid & 31, wid = tid >> 5;
    const int wm = wid >> 1, wn = wid & 1;
    const float* __restrict__ b0 = pb.b[g0];
    const float* __restrict__ b1 = pb.b[g0 + 1];
    float* dst = g_G + ((size_t)pr << 20);
    const bool is_tanh = (pr == 2);
    const int m0 = rowTile + wm * 32 + (lane >> 2);
    const int n0 = colTile + wn * 64 + (lane & 3) * 2;
    #pragma unroll
    for (int mt = 0; mt < 2; mt++)
        #pragma unroll
        for (int h2 = 0; h2 < 2; h2++) {
            const int m = m0 + mt * 16 + h2 * 8;
            const size_t rowb = (size_t)m * NSZ;
            #pragma unroll
            for (int nt = 0; nt < 8; nt++) {
                const size_t idx = rowb + n0 + nt * 8;
                float2 v0 = *(const float2*)(b0 + idx);
                float2 v1 = *(const float2*)(b1 + idx);
                float s0 = acc[mt][nt][h2 * 2 + 0] + v0.x + v1.x;
                float s1 = acc[mt][nt][h2 * 2 + 1] + v0.y + v1.y;
                float2 o;
                if (is_tanh) {
                    o.x = tanhf(s0); o.y = tanhf(s1);
                } else {
                    o.x = 1.0f / (1.0f + __expf(-s0));
                    o.y = 1.0f / (1.0f + __expf(-s1));
                }
                *(float2*)(dst + idx) = o;
            }
        }

    // ---- fused cell: last CTA to finish this 128x128 tile does the LSTM cell
    __threadfence();
    __syncthreads();
    __shared__ int s_last;
    const int tile = blockIdx.y * 8 + blockIdx.x;
    if (tid == 0) {
        int old = atomicAdd(&g_ctr[tile], 1);
        s_last = (old == 3) ? 1 : 0;
    }
    __syncthreads();
    if (s_last) {
        __threadfence();
        const float4* Gi = (const float4*)g_G;
        const float4* Gf = (const float4*)(g_G + (1ul << 20));
        const float4* Gg = (const float4*)(g_G + (2ul << 20));
        const float4* Go = (const float4*)(g_G + (3ul << 20));
        const float4* C  = (const float4*)cin;
        float4* outH = (float4*)out;
        float4* outC = (float4*)(out + (1ul << 20));
        #pragma unroll 4
        for (int it = tid; it < 4096; it += 256) {
            const int rr = it >> 5, cc = it & 31;
            const size_t idx = (size_t)(rowTile + rr) * 256 + (colTile >> 2) + cc;
            float4 vi = Gi[idx], vf = Gf[idx], vg = Gg[idx], vo = Go[idx], vc = C[idx];
            float4 cn, hn;
            cn.x = vf.x * vc.x + vi.x * vg.x;
            cn.y = vf.y * vc.y + vi.y * vg.y;
            cn.z = vf.z * vc.z + vi.z * vg.z;
            cn.w = vf.w * vc.w + vi.w * vg.w;
            hn.x = vo.x * tanhf(cn.x);
            hn.y = vo.y * tanhf(cn.y);
            hn.z = vo.z * tanhf(cn.z);
            hn.w = vo.w * tanhf(cn.w);
            outH[idx] = hn;
            outC[idx] = cn;
        }
        if (tid == 0) g_ctr[tile] = 0;
    }
}

// ---------------- Conversion kernel: L (elementwise) + x,h (transpose) ------
struct PC { const float* L[8]; const float* xh[2]; };

__global__ void __launch_bounds__(256)
convAll(PC p)
{
    const int z = blockIdx.z;
    const int tid = threadIdx.x;
    if (z < 8) {
        #pragma unroll
        for (int i = 0; i < 4; i++) {
            const size_t idx = (size_t)blockIdx.x * 1024 + i * 256 + tid;
            float4 v = ((const float4*)p.L[z])[idx];
            __half2 hA = __floats2half2_rn(v.x, v.y);
            __half2 hB = __floats2half2_rn(v.z, v.w);
            ((uint2*)(g_Lh + ((size_t)z << 20)))[idx] =
                make_uint2(*(uint32_t*)&hA, *(uint32_t*)&hB);
        }
    } else {
        __shared__ float t[64 * 65];
        const int zz = z - 8;
        const int tile = blockIdx.x;                 // 0..255
        const int k0 = (tile & 15) * 64, n0 = (tile >> 4) * 64;
        transpose64(p.xh[zz], g_XTh + ((size_t)zz << 20), k0, n0, t, tid);
    }
}

// ---------------- launch -----------------------------------------------------
extern "C" void kernel_launch(void* const* d_in, const int* in_sizes, int n_in,
                              void* d_out, int out_size)
{
    (void)in_sizes; (void)n_in; (void)out_size;
    const float* x = (const float*)d_in[0];
    const float* h = (const float*)d_in[1];
    const float* c = (const float*)d_in[2];

    B8 pB;
    PC pc;
    PR pr;
    pc.xh[0] = x;
    pc.xh[1] = h;
    for (int g = 0; g < 8; g++) {
        pc.L[g] = (const float*)d_in[3 + 3 * g];   // L_g
        pr.R[g] = (const float*)d_in[4 + 3 * g];   // R_g (transposed inside gemm1)
        pB.b[g] = (const float*)d_in[5 + 3 * g];   // b_g
    }

    cudaFuncSetAttribute(gemm1, cudaFuncAttributeMaxDynamicSharedMemorySize, GEMM_SMEM);
    cudaFuncSetAttribute(gemm2, cudaFuncAttributeMaxDynamicSharedMemorySize, GEMM_SMEM);

    convAll<<<dim3(256, 1, 10), 256>>>(pc);
    gemm1<<<dim3(8, 8, 9), 256, GEMM_SMEM>>>(pr);
    gemm2<<<dim3(8, 8, 4), 256, GEMM_SMEM>>>(pB, c, (float*)d_out);
}

// round 16
// speedup vs baseline: 1.3672x; 1.3672x over previous
#include <cuda_runtime.h>
#include <cuda_fp16.h>
#include <cstdint>
#include <math.h>

#define NSZ 1024

// ---------------- scratch (static device globals; no runtime alloc) --------
__device__ __align__(16) __half g_Lh[8u << 20];
__device__ __align__(16) __half g_XTh[2u << 20];
__device__ __align__(16) __half g_RTh[8u << 20];
__device__ __align__(16) __half g_Ph[8u << 20];
__device__ __align__(16) float g_G[4u << 20];
__device__ int g_ctr[64];   // per-output-tile gate counters (zero-init; reset after use)

// stage holds k=64: A0 8K | A1 8K | B0 8K | B1 8K = 32K; ring depth 3 = 96K
#define NST 3
#define STAGE 32768
#define OFF_B 16384
#define GEMM_SMEM (NST * STAGE + 128)

// ---------------- PTX helpers (all baseline sm_80/90-level) -----------------
__device__ __forceinline__ uint32_t smem_u32(const void* p) {
    uint32_t a;
    asm("{ .reg .u64 t; cvta.to.shared.u64 t, %1; cvt.u32.u64 %0, t; }"
        : "=r"(a) : "l"(p));
    return a;
}
__device__ __forceinline__ void cp16(uint32_t smem, const void* g) {
    asm volatile("cp.async.cg.shared.global [%0], [%1], 16;"
                 :: "r"(smem), "l"(g));
}
__device__ __forceinline__ void mbar_init(uint32_t a, uint32_t cnt) {
    asm volatile("mbarrier.init.shared.b64 [%0], %1;" :: "r"(a), "r"(cnt) : "memory");
}
__device__ __forceinline__ void mbar_arrive(uint32_t a) {
    asm volatile("mbarrier.arrive.shared.b64 _, [%0];" :: "r"(a) : "memory");
}
__device__ __forceinline__ void cp_mbar_arrive(uint32_t a) {
    asm volatile("cp.async.mbarrier.arrive.noinc.shared.b64 [%0];" :: "r"(a) : "memory");
}
__device__ __forceinline__ void mbar_wait(uint32_t a, uint32_t phase) {
    asm volatile("{\n\t.reg .pred P;\n\tWL%=:\n\t"
                 "mbarrier.try_wait.parity.acquire.cta.shared::cta.b64 P, [%0], %1, 0x989680;\n\t"
                 "@!P bra WL%=;\n\t}" :: "r"(a), "r"(phase) : "memory");
}
__device__ __forceinline__ void ldsm_x4(uint32_t (&r)[4], uint32_t addr) {
    asm volatile("ldmatrix.sync.aligned.m8n8.x4.shared.b16 {%0,%1,%2,%3}, [%4];"
                 : "=r"(r[0]), "=r"(r[1]), "=r"(r[2]), "=r"(r[3]) : "r"(addr));
}
__device__ __forceinline__ void mma16816(float (&d)[4], const uint32_t (&a)[4],
                                         uint32_t b0, uint32_t b1) {
    asm volatile("mma.sync.aligned.m16n8k16.row.col.f32.f16.f16.f32 "
                 "{%0,%1,%2,%3}, {%4,%5,%6,%7}, {%8,%9}, {%0,%1,%2,%3};"
                 : "+f"(d[0]), "+f"(d[1]), "+f"(d[2]), "+f"(d[3])
                 : "r"(a[0]), "r"(a[1]), "r"(a[2]), "r"(a[3]), "r"(b0), "r"(b1));
}

// swizzle: 16B chunk j within 64B row r -> j ^ ((r>>1)&3)
__device__ __forceinline__ uint32_t sw_off(int r, int j) {
    return (uint32_t)(r * 64 + ((j ^ ((r >> 1) & 3)) << 4));
}

// load one [128 rows x 32 k] fp16 tile into swizzled SMEM via cp.async
__device__ __forceinline__ void issue_mat(const __half* __restrict__ src,
                                          int row0, int k0, uint32_t dst, int tid) {
    #pragma unroll
    for (int i = 0; i < 2; i++) {
        int f = tid + i * 256;
        int r = f >> 2;
        int j = f & 3;
        cp16(dst + sw_off(r, j), src + (size_t)(row0 + r) * NSZ + k0 + j * 8);
    }
}

// issue one k=64 stage (two k=32 sub-tiles per matrix)
__device__ __forceinline__ void issue_stage(uint32_t base,
    const __half* Ah, const __half* Bh, int rowTile, int colTile, int k0, int tid)
{
    issue_mat(Ah, rowTile, k0,      base,                tid);
    issue_mat(Ah, rowTile, k0 + 32, base + 8192,         tid);
    issue_mat(Bh, colTile, k0,      base + OFF_B,        tid);
    issue_mat(Bh, colTile, k0 + 32, base + OFF_B + 8192, tid);
}

// ---------------- fp16 GEMM mainloop (k=64 stages, mbarrier ring depth 3) ---
__device__ __forceinline__ void mainloop(
    uint32_t sb, int tid, int nhalf,
    const __half* const* Ah, const __half* const* Bh,
    int rowTile, int colTile, float (&acc)[2][8][4])
{
    const uint32_t fullB  = sb + NST * STAGE;
    const uint32_t emptyB = fullB + NST * 8;

    const int lane = tid & 31;
    const int wid  = tid >> 5;
    const int wm   = wid >> 1;       // 0..3  (32 rows)
    const int wn   = wid & 1;        // 0..1  (64 cols)

    if (tid == 0) {
        #pragma unroll
        for (int b = 0; b < NST; b++) {
            mbar_init(fullB  + b * 8, 256);
            mbar_init(emptyB + b * 8, 256);
        }
    }
    __syncthreads();   // inits visible before any arrive

    uint32_t aOff[2][2], bOff[2][4];
    #pragma unroll
    for (int ks = 0; ks < 2; ks++) {
        #pragma unroll
        for (int mt = 0; mt < 2; mt++) {
            int r = wm * 32 + mt * 16 + (lane & 15);
            int j = ks * 2 + (lane >> 4);
            aOff[ks][mt] = sw_off(r, j);
        }
        #pragma unroll
        for (int bp = 0; bp < 4; bp++) {
            int r = wn * 64 + bp * 16 + ((lane >> 4) * 8) + (lane & 7);
            int j = ks * 2 + ((lane >> 3) & 1);
            bOff[ks][bp] = sw_off(r, j);
        }
    }

    const int NS = 16 * nhalf;   // k=64 stages

    #pragma unroll
    for (int s = 0; s < NST; s++) {
        issue_stage(sb + s * STAGE, Ah[0], Bh[0], rowTile, colTile, s * 64, tid);
        cp_mbar_arrive(fullB + s * 8);
    }

    uint32_t fmask = 0, emask = 0;
    int b = 0;
    #pragma unroll 1
    for (int s = 0; s < NS; s++) {
        mbar_wait(fullB + b * 8, (fmask >> b) & 1);
        fmask ^= 1u << b;

        const uint32_t base = sb + b * STAGE;
        #pragma unroll
        for (int sub = 0; sub < 2; sub++) {
            const uint32_t abase = base + sub * 8192;
            const uint32_t bbase = base + OFF_B + sub * 8192;
            #pragma unroll
            for (int ks = 0; ks < 2; ks++) {
                uint32_t Af[2][4], Bf[4][4];
                #pragma unroll
                for (int mt = 0; mt < 2; mt++) ldsm_x4(Af[mt], abase + aOff[ks][mt]);
                #pragma unroll
                for (int bp = 0; bp < 4; bp++) ldsm_x4(Bf[bp], bbase + bOff[ks][bp]);
                if (sub == 1 && ks == 1) mbar_arrive(emptyB + b * 8);

                #pragma unroll
                for (int mt = 0; mt < 2; mt++)
                    #pragma unroll
                    for (int nt = 0; nt < 8; nt++)
                        mma16816(acc[mt][nt], Af[mt],
                                 Bf[nt >> 1][(nt & 1) * 2], Bf[nt >> 1][(nt & 1) * 2 + 1]);
            }
        }

        const int sn = s + NST;
        if (sn < NS) {
            mbar_wait(emptyB + b * 8, (emask >> b) & 1);
            emask ^= 1u << b;
            const int hf = sn >> 4;
            const int k0 = (sn & 15) * 64;
            issue_stage(base, Ah[hf], Bh[hf], rowTile, colTile, k0, tid);
            cp_mbar_arrive(fullB + b * 8);
        }
        b = (b + 1 == NST) ? 0 : b + 1;
    }
}

// ---------------- Kernel: phase 1  P_g = Lh @ Xh -----------------------------
__global__ void __launch_bounds__(256, 2)
gemm1()
{
    extern __shared__ char smem[];
    const uint32_t sb = smem_u32(smem);
    const int tid = threadIdx.x;
    const int gate = blockIdx.z;
    const int rowTile = blockIdx.y * 128, colTile = blockIdx.x * 128;

    float acc[2][8][4];
    #pragma unroll
    for (int a = 0; a < 2; a++)
        #pragma unroll
        for (int b = 0; b < 8; b++)
            #pragma unroll
            for (int e = 0; e < 4; e++) acc[a][b][e] = 0.0f;

    const __half* Ah[2] = { g_Lh  + ((size_t)gate << 20), nullptr };
    const __half* Bh[2] = { g_XTh + ((size_t)(gate & 1) << 20), nullptr };

    mainloop(sb, tid, 1, Ah, Bh, rowTile, colTile, acc);

    // epilogue: store P as fp16
    const int lane = tid & 31, wid = tid >> 5;
    const int wm = wid >> 1, wn = wid & 1;
    __half* dh = g_Ph + ((size_t)gate << 20);
    const int m0 = rowTile + wm * 32 + (lane >> 2);
    const int n0 = colTile + wn * 64 + (lane & 3) * 2;
    #pragma unroll
    for (int mt = 0; mt < 2; mt++)
        #pragma unroll
        for (int h2 = 0; h2 < 2; h2++) {
            const int m = m0 + mt * 16 + h2 * 8;
            const size_t rowb = (size_t)m * NSZ;
            #pragma unroll
            for (int nt = 0; nt < 8; nt++) {
                __half2 hp = __floats2half2_rn(acc[mt][nt][h2 * 2 + 0],
                                               acc[mt][nt][h2 * 2 + 1]);
                *(uint32_t*)(dh + rowb + n0 + nt * 8) = *(uint32_t*)&hp;
            }
        }
}

// ---------------- Kernel: phase 2  gates + fused LSTM cell -------------------
struct B8 { const float* b[8]; };

__global__ void __launch_bounds__(256, 2)
gemm2(B8 pb, const float* __restrict__ cin, float* __restrict__ out)
{
    extern __shared__ char smem[];
    const uint32_t sb = smem_u32(smem);
    const int tid = threadIdx.x;
    const int pr = blockIdx.z;                 // 0:i 1:f 2:g 3:o
    const int g0 = 2 * pr;
    const int rowTile = blockIdx.y * 128, colTile = blockIdx.x * 128;

    float acc[2][8][4];
    #pragma unroll
    for (int a = 0; a < 2; a++)
        #pragma unroll
        for (int b = 0; b < 8; b++)
            #pragma unroll
            for (int e = 0; e < 4; e++) acc[a][b][e] = 0.0f;

    const __half* Ah[2] = { g_Ph  + ((size_t)g0 << 20), g_Ph  + ((size_t)(g0 + 1) << 20) };
    const __half* Bh[2] = { g_RTh + ((size_t)g0 << 20), g_RTh + ((size_t)(g0 + 1) << 20) };

    mainloop(sb, tid, 2, Ah, Bh, rowTile, colTile, acc);

    // epilogue: + b0 + b1, activation, store fp32 gate
    const int lane = tid & 31, wid = tid >> 5;
    const int wm = wid >> 1, wn = wid & 1;
    const float* __restrict__ b0 = pb.b[g0];
    const float* __restrict__ b1 = pb.b[g0 + 1];
    float* dst = g_G + ((size_t)pr << 20);
    const bool is_tanh = (pr == 2);
    const int m0 = rowTile + wm * 32 + (lane >> 2);
    const int n0 = colTile + wn * 64 + (lane & 3) * 2;
    #pragma unroll
    for (int mt = 0; mt < 2; mt++)
        #pragma unroll
        for (int h2 = 0; h2 < 2; h2++) {
            const int m = m0 + mt * 16 + h2 * 8;
            const size_t rowb = (size_t)m * NSZ;
            #pragma unroll
            for (int nt = 0; nt < 8; nt++) {
                const size_t idx = rowb + n0 + nt * 8;
                float2 v0 = *(const float2*)(b0 + idx);
                float2 v1 = *(const float2*)(b1 + idx);
                float s0 = acc[mt][nt][h2 * 2 + 0] + v0.x + v1.x;
                float s1 = acc[mt][nt][h2 * 2 + 1] + v0.y + v1.y;
                float2 o;
                if (is_tanh) {
                    o.x = tanhf(s0); o.y = tanhf(s1);
                } else {
                    o.x = 1.0f / (1.0f + __expf(-s0));
                    o.y = 1.0f / (1.0f + __expf(-s1));
                }
                *(float2*)(dst + idx) = o;
            }
        }

    // ---- fused cell: last CTA to finish this 128x128 tile does the LSTM cell
    __threadfence();
    __syncthreads();
    __shared__ int s_last;
    const int tile = blockIdx.y * 8 + blockIdx.x;
    if (tid == 0) {
        int old = atomicAdd(&g_ctr[tile], 1);
        s_last = (old == 3) ? 1 : 0;
    }
    __syncthreads();
    if (s_last) {
        __threadfence();
        const float4* Gi = (const float4*)g_G;
        const float4* Gf = (const float4*)(g_G + (1ul << 20));
        const float4* Gg = (const float4*)(g_G + (2ul << 20));
        const float4* Go = (const float4*)(g_G + (3ul << 20));
        const float4* C  = (const float4*)cin;
        float4* outH = (float4*)out;
        float4* outC = (float4*)(out + (1ul << 20));
        #pragma unroll 4
        for (int it = tid; it < 4096; it += 256) {
            const int rr = it >> 5, cc = it & 31;
            const size_t idx = (size_t)(rowTile + rr) * 256 + (colTile >> 2) + cc;
            float4 vi = Gi[idx], vf = Gf[idx], vg = Gg[idx], vo = Go[idx], vc = C[idx];
            float4 cn, hn;
            cn.x = vf.x * vc.x + vi.x * vg.x;
            cn.y = vf.y * vc.y + vi.y * vg.y;
            cn.z = vf.z * vc.z + vi.z * vg.z;
            cn.w = vf.w * vc.w + vi.w * vg.w;
            hn.x = vo.x * tanhf(cn.x);
            hn.y = vo.y * tanhf(cn.y);
            hn.z = vo.z * tanhf(cn.z);
            hn.w = vo.w * tanhf(cn.w);
            outH[idx] = hn;
            outC[idx] = cn;
        }
        if (tid == 0) g_ctr[tile] = 0;
    }
}

// ---------------- Merged conversion kernel -----------------------------------
// z 0..7  : L_g fp32 -> fp16 elementwise (grid.x = 1024, 1 float4/thread)
// z 8..17 : transpose+convert (x, h, R_0..7) via 64x64 tiles, half2 writes
//           (only blockIdx.x < 256 participate; one tile per CTA)
struct PC { const float* L[8]; const float* T[10]; };

__global__ void __launch_bounds__(256)
convAll(PC p)
{
    const int z = blockIdx.z;
    const int tid = threadIdx.x;
    if (z < 8) {
        const size_t i = (size_t)blockIdx.x * 256 + tid;   // float4 index
        float4 v = ((const float4*)p.L[z])[i];
        __half2 hA = __floats2half2_rn(v.x, v.y);
        __half2 hB = __floats2half2_rn(v.z, v.w);
        ((uint2*)(g_Lh + ((size_t)z << 20)))[i] = make_uint2(*(uint32_t*)&hA, *(uint32_t*)&hB);
    } else {
        if (blockIdx.x >= 256) return;
        __shared__ float t[64 * 65];
        const int zz = z - 8;
        const float* __restrict__ src = p.T[zz];
        __half* dh = (zz < 2) ? g_XTh + ((size_t)zz << 20)
                              : g_RTh + ((size_t)(zz - 2) << 20);
        const int k0 = (blockIdx.x & 15) * 64, n0 = (blockIdx.x >> 4) * 64;
        // coalesced float4 reads: src[k][n]
        #pragma unroll
        for (int i = 0; i < 4; i++) {
            int f = tid + i * 256;
            int kk = f >> 4;               // 0..63
            int c4 = (f & 15) << 2;        // 0..60
            float4 v = *(const float4*)(src + (size_t)(k0 + kk) * NSZ + n0 + c4);
            t[kk * 65 + c4 + 0] = v.x;
            t[kk * 65 + c4 + 1] = v.y;
            t[kk * 65 + c4 + 2] = v.z;
            t[kk * 65 + c4 + 3] = v.w;
        }
        __syncthreads();
        // 128B/warp half2 writes: dst[n][k]
        #pragma unroll
        for (int i = 0; i < 8; i++) {
            int f = tid + i * 256;
            int nn = f >> 5;               // 0..63
            int pp = f & 31;               // k-pair 0..31
            __half2 hp = __floats2half2_rn(t[(2 * pp) * 65 + nn],
                                           t[(2 * pp + 1) * 65 + nn]);
            *(uint32_t*)(dh + (size_t)(n0 + nn) * NSZ + k0 + 2 * pp) = *(uint32_t*)&hp;
        }
    }
}

// ---------------- launch -----------------------------------------------------
extern "C" void kernel_launch(void* const* d_in, const int* in_sizes, int n_in,
                              void* d_out, int out_size)
{
    (void)in_sizes; (void)n_in; (void)out_size;
    const float* x = (const float*)d_in[0];
    const float* h = (const float*)d_in[1];
    const float* c = (const float*)d_in[2];

    B8 pB;
    PC pc;
    pc.T[0] = x;
    pc.T[1] = h;
    for (int g = 0; g < 8; g++) {
        pc.L[g]     = (const float*)d_in[3 + 3 * g];   // L_g
        pc.T[2 + g] = (const float*)d_in[4 + 3 * g];   // R_g (transposed)
        pB.b[g]     = (const float*)d_in[5 + 3 * g];   // b_g
    }

    cudaFuncSetAttribute(gemm1, cudaFuncAttributeMaxDynamicSharedMemorySize, GEMM_SMEM);
    cudaFuncSetAttribute(gemm2, cudaFuncAttributeMaxDynamicSharedMemorySize, GEMM_SMEM);

    convAll<<<dim3(1024, 1, 18), 256>>>(pc);
    gemm1<<<dim3(8, 8, 8), 256, GEMM_SMEM>>>();
    gemm2<<<dim3(8, 8, 4), 256, GEMM_SMEM>>>(pB, c, (float*)d_out);
}